// round 3
// baseline (speedup 1.0000x reference)
#include <cuda_runtime.h>
#include <cuda_fp16.h>
#include <stdint.h>

// ---------------- problem constants ----------------
#define HID     2048
#define BATCHN  64
#define G4      8192
#define NSTEPS  30
#define NTILE   128           // M tiles of 64 gate-rows -> 128 CTAs
#define NKCH    32            // K chunks of 64 fp16 (128B rows, SW128)
#define WCH     8192          // bytes per W chunk tile (64 rows x 128B)
#define HCH     8192          // bytes per h chunk tile (64 rows x 128B)
#define STG     24576         // stage = Whi 8K + Wlo 8K + h 8K
#define NSTG    4
#define SMEM_REQ (NSTG*STG + 1024)

// ---------------- device scratch (static, no allocs) ----------------
__device__ __align__(1024) unsigned char g_wsum_hi[NTILE*NKCH*WCH]; // 32MB
__device__ __align__(1024) unsigned char g_wsum_lo[NTILE*NKCH*WCH];
__device__ __align__(1024) unsigned char g_whh_hi [NTILE*NKCH*WCH];
__device__ __align__(1024) unsigned char g_whh_lo [NTILE*NKCH*WCH];
__device__ __align__(1024) unsigned char g_hA[NKCH*HCH];            // 256KB tiled fp16 h
__device__ __align__(1024) unsigned char g_hB[NKCH*HCH];
__device__ float g_c[BATCHN*HID];
__device__ float g_bias[G4];
__device__ float g_hist[NSTEPS*BATCHN*HID];

// ---------------- helpers ----------------
__device__ __forceinline__ uint32_t smem_u32(const void* p) {
    uint32_t a;
    asm("{ .reg .u64 t; cvta.to.shared.u64 t, %1; cvt.u32.u64 %0, t; }" : "=r"(a) : "l"(p));
    return a;
}
__device__ __forceinline__ uint32_t swz(uint32_t o) { return o ^ ((o >> 3) & 0x70); }

__device__ __forceinline__ void ldm4(uint32_t* r, uint32_t a) {
    asm volatile("ldmatrix.sync.aligned.m8n8.x4.shared.b16 {%0,%1,%2,%3}, [%4];"
                 : "=r"(r[0]), "=r"(r[1]), "=r"(r[2]), "=r"(r[3]) : "r"(a));
}
__device__ __forceinline__ void mma16816(float* d, const uint32_t* a, uint32_t b0, uint32_t b1) {
    asm volatile("mma.sync.aligned.m16n8k16.row.col.f32.f16.f16.f32 "
                 "{%0,%1,%2,%3}, {%4,%5,%6,%7}, {%8,%9}, {%0,%1,%2,%3};"
                 : "+f"(d[0]), "+f"(d[1]), "+f"(d[2]), "+f"(d[3])
                 : "r"(a[0]), "r"(a[1]), "r"(a[2]), "r"(a[3]), "r"(b0), "r"(b1));
}
__device__ __forceinline__ void cp16(uint32_t dst, const void* src) {
    asm volatile("cp.async.cg.shared.global [%0], [%1], 16;" :: "r"(dst), "l"(src) : "memory");
}
__device__ __forceinline__ float sigm(float x) {
    x = fminf(15.f, fmaxf(-15.f, x));
    return 1.f / (1.f + __expf(-x));
}
__device__ __forceinline__ float tanh_(float x) {
    x = fminf(8.f, fmaxf(-8.f, x));
    float e = __expf(-2.f * x);
    return (1.f - e) / (1.f + e);
}

// ---------------- prep: tiled + SW128-swizzled hi/lo fp16 weights ----------------
// Tile t (0..127), row r (0..63): gate = r>>4, unit = r&15 -> orig row gate*HID + t*16 + unit.
__global__ void prep_weights(const float* __restrict__ Wih, const float* __restrict__ Whh) {
    int id  = blockIdx.x * 256 + threadIdx.x;     // 8,388,608 (one half2 pair each)
    int cp  = id & 31;
    int row = (id >> 5) & 63;
    int kc  = (id >> 11) & 31;
    int t   = id >> 16;
    int gate = row >> 4, u = row & 15;
    long orow = (long)gate * HID + t * 16 + u;
    int  ocol = kc * 64 + cp * 2;
    float2 wi = *(const float2*)(Wih + orow * HID + ocol);
    float2 wh = *(const float2*)(Whh + orow * HID + ocol);
    float sx = wi.x + wh.x, sy = wi.y + wh.y;
    __half shx = __float2half_rn(sx),  shy = __float2half_rn(sy);
    __half slx = __float2half_rn(sx - __half2float(shx));
    __half sly = __float2half_rn(sy - __half2float(shy));
    __half hhx = __float2half_rn(wh.x), hhy = __float2half_rn(wh.y);
    __half hlx = __float2half_rn(wh.x - __half2float(hhx));
    __half hly = __float2half_rn(wh.y - __half2float(hhy));
    uint32_t toff = (uint32_t)(t * NKCH + kc) * WCH + swz((uint32_t)(row * 128 + cp * 4));
    *(__half2*)(g_wsum_hi + toff) = __halves2half2(shx, shy);
    *(__half2*)(g_wsum_lo + toff) = __halves2half2(slx, sly);
    *(__half2*)(g_whh_hi  + toff) = __halves2half2(hhx, hhy);
    *(__half2*)(g_whh_lo  + toff) = __halves2half2(hlx, hly);
}

// zero c, fused bias, tiled fp16 h0 into buffer A
__global__ void prep_misc(const float* __restrict__ tok,
                          const float* __restrict__ bih, const float* __restrict__ bhh) {
    int id = blockIdx.x * 256 + threadIdx.x;      // 131072
    float h0 = tok[id];
    g_c[id] = 0.0f;
    int b = id >> 11, hid = id & 2047;
    int kc = hid >> 6, cc = hid & 63;
    uint32_t off = (uint32_t)kc * HCH + swz((uint32_t)(b * 128 + cc * 2));
    *(__half*)(g_hA + off) = __float2half_rn(h0);
    if (id < G4) g_bias[id] = bih[id] + bhh[id];
}

// ---------------- one LSTM step: gates = W x h^T, fused LSTM epilogue ----------------
__global__ void __launch_bounds__(256, 1) lstm_step(int step) {
    extern __shared__ unsigned char smraw[];
    uint32_t sbr  = smem_u32(smraw);
    uint32_t base = (sbr + 1023) & ~1023u;
    unsigned char* gbase = smraw + (base - sbr);

    int tid = threadIdx.x;
    int lane = tid & 31, wid = tid >> 5;
    int warp_m = wid & 3;        // gate
    int warp_n = wid >> 2;       // batch half
    int blk = blockIdx.x;

    const unsigned char* whi = (step ? g_wsum_hi : g_whh_hi) + (size_t)blk * NKCH * WCH;
    const unsigned char* wlo = (step ? g_wsum_lo : g_whh_lo) + (size_t)blk * NKCH * WCH;
    const unsigned char* hsrc = (step & 1) ? g_hB : g_hA;

    // per-lane ldmatrix address components
    uint32_t a_row  = (uint32_t)(warp_m * 16 + (lane & 15));
    uint32_t a_colb = (uint32_t)((lane >> 4) << 4);
    uint32_t b_row  = (uint32_t)(warp_n * 32 + (lane & 7) + ((lane >> 4) << 3));
    uint32_t b_colb = (uint32_t)(((lane >> 3) & 1) << 4);

    float acc[16];
    #pragma unroll
    for (int i = 0; i < 16; i++) acc[i] = 0.f;

    // prefetch chunks 0..2
    #pragma unroll
    for (int c = 0; c < 3; c++) {
        uint32_t sb = base + (uint32_t)c * STG;
        size_t go = (size_t)c * WCH;
        #pragma unroll
        for (int r = 0; r < 2; r++) {
            int o = (r * 256 + tid) * 16;
            cp16(sb + o,         whi + go + o);
            cp16(sb + 8192 + o,  wlo + go + o);
            cp16(sb + 16384 + o, hsrc + (size_t)c * HCH + o);
        }
        asm volatile("cp.async.commit_group;" ::: "memory");
    }

    for (int kc = 0; kc < NKCH; kc++) {
        if (kc <= 29)      asm volatile("cp.async.wait_group 2;" ::: "memory");
        else if (kc == 30) asm volatile("cp.async.wait_group 1;" ::: "memory");
        else               asm volatile("cp.async.wait_group 0;" ::: "memory");
        __syncthreads();

        int nc = kc + 3;
        if (nc < NKCH) {
            uint32_t sb = base + (uint32_t)(nc & 3) * STG;
            size_t go = (size_t)nc * WCH;
            #pragma unroll
            for (int r = 0; r < 2; r++) {
                int o = (r * 256 + tid) * 16;
                cp16(sb + o,         whi + go + o);
                cp16(sb + 8192 + o,  wlo + go + o);
                cp16(sb + 16384 + o, hsrc + (size_t)nc * HCH + o);
            }
            asm volatile("cp.async.commit_group;" ::: "memory");
        }

        uint32_t sb  = base + (uint32_t)(kc & 3) * STG;
        uint32_t shi = sb, slo = sb + 8192, shb = sb + 16384;
        #pragma unroll
        for (int ks = 0; ks < 4; ks++) {
            uint32_t ao = swz(a_row * 128 + (uint32_t)ks * 32 + a_colb);
            uint32_t ah[4], al[4], bb[8];
            ldm4(ah, shi + ao);
            ldm4(al, slo + ao);
            ldm4(bb,     shb + swz(b_row * 128 + (uint32_t)ks * 32 + b_colb));
            ldm4(bb + 4, shb + swz((b_row + 16) * 128 + (uint32_t)ks * 32 + b_colb));
            #pragma unroll
            for (int g = 0; g < 4; g++) {
                mma16816(acc + 4 * g, ah, bb[2 * g], bb[2 * g + 1]);
                mma16816(acc + 4 * g, al, bb[2 * g], bb[2 * g + 1]);
            }
        }
    }
    __syncthreads();

    // ---- exchange: smx[gate][batch][unit], 4*64*16 fp32 = 16KB (reuse stage 0) ----
    float* smx = (float*)gbase;
    #pragma unroll
    for (int g = 0; g < 4; g++) {
        int n0 = warp_n * 32 + 8 * g + 2 * (lane & 3);
        int u0 = lane >> 2;
        smx[(warp_m * 64 + n0    ) * 16 + u0    ] = acc[4 * g + 0];
        smx[(warp_m * 64 + n0 + 1) * 16 + u0    ] = acc[4 * g + 1];
        smx[(warp_m * 64 + n0    ) * 16 + u0 + 8] = acc[4 * g + 2];
        smx[(warp_m * 64 + n0 + 1) * 16 + u0 + 8] = acc[4 * g + 3];
    }
    __syncthreads();

    unsigned char* hout = (step & 1) ? g_hA : g_hB;
    #pragma unroll
    for (int k = 0; k < 4; k++) {
        int p = k * 256 + tid;          // 0..1023 = (unit, batch)
        int u = p & 15, b = p >> 4;
        int hid = blk * 16 + u;
        float xi = smx[(0 * 64 + b) * 16 + u] + g_bias[hid];
        float xf = smx[(1 * 64 + b) * 16 + u] + g_bias[2048 + hid];
        float xg = smx[(2 * 64 + b) * 16 + u] + g_bias[4096 + hid];
        float xo = smx[(3 * 64 + b) * 16 + u] + g_bias[6144 + hid];
        float ii = sigm(xi), ff = sigm(xf), gg = tanh_(xg), oo = sigm(xo);
        int ci = b * HID + hid;
        float c = ff * g_c[ci] + ii * gg;
        g_c[ci] = c;
        float h = oo * tanh_(c);
        g_hist[((size_t)step * BATCHN + b) * HID + hid] = h;
        uint32_t off = (uint32_t)(hid >> 6) * HCH + swz((uint32_t)(b * 128 + (hid & 63) * 2));
        *(__half*)(hout + off) = __float2half_rn(h);
    }
}

// ---------------- output projection: y[b,t] = hist[t,b,:] . W_out + b_out ----------------
__global__ void out_kernel(const float* __restrict__ Wout, const float* __restrict__ bout,
                           float* __restrict__ out) {
    int t = blockIdx.x / BATCHN;
    int b = blockIdx.x % BATCHN;
    const float* h = g_hist + ((size_t)t * BATCHN + b) * HID;
    float acc = 0.f;
    for (int k = threadIdx.x; k < HID; k += 128) acc += h[k] * Wout[k];
    #pragma unroll
    for (int o = 16; o; o >>= 1) acc += __shfl_xor_sync(0xFFFFFFFFu, acc, o);
    __shared__ float ws[4];
    if ((threadIdx.x & 31) == 0) ws[threadIdx.x >> 5] = acc;
    __syncthreads();
    if (threadIdx.x == 0)
        out[b * NSTEPS + t] = ws[0] + ws[1] + ws[2] + ws[3] + bout[0];
}

// ---------------- launch ----------------
extern "C" void kernel_launch(void* const* d_in, const int* in_sizes, int n_in,
                              void* d_out, int out_size) {
    int wi = (n_in >= 8) ? 2 : 1;   // skip scalar `steps` input if present
    const float* tok  = (const float*)d_in[0];
    const float* Wih  = (const float*)d_in[wi];
    const float* Whh  = (const float*)d_in[wi + 1];
    const float* bih  = (const float*)d_in[wi + 2];
    const float* bhh  = (const float*)d_in[wi + 3];
    const float* Wout = (const float*)d_in[wi + 4];
    const float* bout = (const float*)d_in[wi + 5];
    float* out = (float*)d_out;

    cudaFuncSetAttribute(lstm_step, cudaFuncAttributeMaxDynamicSharedMemorySize, SMEM_REQ);

    prep_weights<<<32768, 256>>>(Wih, Whh);
    prep_misc<<<512, 256>>>(tok, bih, bhh);
    for (int t = 0; t < NSTEPS; t++)
        lstm_step<<<NTILE, 256, SMEM_REQ>>>(t);
    out_kernel<<<NSTEPS * BATCHN, 128>>>(Wout, bout, out);
}